// round 15
// baseline (speedup 1.0000x reference)
#include <cuda_runtime.h>
#include <cuda_fp16.h>
#include <math.h>
#include <stdint.h>

#define B_DIM 2
#define NUM_HEADS 32
#define NUM_KV 8
#define SEQ 2048
#define DM 2048
#define HD 64
#define MTOT (B_DIM * SEQ)

// fp16 scratch (allocation-free device globals)
__device__ __half g_xh[(size_t)MTOT * DM];
__device__ __half g_wq[(size_t)DM * DM];
__device__ __half g_wk[(size_t)DM * 512];
__device__ __half g_wv[(size_t)DM * 512];
__device__ __half g_wo[(size_t)DM * DM];
__device__ __half g_q[(size_t)B_DIM * NUM_HEADS * SEQ * HD];
__device__ __half g_k[(size_t)B_DIM * NUM_KV * SEQ * HD];
__device__ __half g_v[(size_t)B_DIM * NUM_KV * SEQ * HD];
__device__ __half g_ao[(size_t)MTOT * DM];
__device__ float  g_rope[SEQ * 32 * 2];

// softmax scale folded into Q at projection time: 1/sqrt(64) * log2(e)
#define QSCALE 0.1803368801111204f

// ---------------------------------------------------------------------------
// Fused prologue: all fp32->fp16 conversions + RoPE table in ONE launch.
// ---------------------------------------------------------------------------
__global__ void prep(const float4* __restrict__ x, const float4* __restrict__ wq,
                     const float4* __restrict__ wk, const float4* __restrict__ wv,
                     const float4* __restrict__ wo)
{
    const int b = blockIdx.x, tid = threadIdx.x;
    const float4* src;
    __half* dst;
    int base;
    if (b < 8192)       { src = x;  dst = g_xh; base = 0; }
    else if (b < 12288) { src = wq; dst = g_wq; base = 8192; }
    else if (b < 13312) { src = wk; dst = g_wk; base = 12288; }
    else if (b < 14336) { src = wv; dst = g_wv; base = 13312; }
    else if (b < 18432) { src = wo; dst = g_wo; base = 14336; }
    else {
        int i = (b - 18432) * 256 + tid;
        int s = i >> 5, j = i & 31;
        float inv = expf(-(float)j * 0.28782313662425572f);
        float sv, cv;
        sincosf((float)s * inv, &sv, &cv);
        g_rope[(size_t)i * 2 + 0] = cv;
        g_rope[(size_t)i * 2 + 1] = sv;
        return;
    }
    size_t i = (size_t)(b - base) * 256 + tid;
    float4 v = src[i];
    __half2* d = (__half2*)(dst + i * 4);
    d[0] = __floats2half2_rn(v.x, v.y);
    d[1] = __floats2half2_rn(v.z, v.w);
}

// ---------------------------------------------------------------------------
// Helpers
// ---------------------------------------------------------------------------
__device__ __forceinline__ uint32_t smem_u32(const void* p)
{
    return (uint32_t)__cvta_generic_to_shared(p);
}
__device__ __forceinline__ void ldmx4(uint32_t* r, uint32_t a)
{
    asm volatile("ldmatrix.sync.aligned.m8n8.x4.shared.b16 {%0,%1,%2,%3}, [%4];"
                 : "=r"(r[0]), "=r"(r[1]), "=r"(r[2]), "=r"(r[3]) : "r"(a));
}
__device__ __forceinline__ void ldmx4t(uint32_t* r, uint32_t a)
{
    asm volatile("ldmatrix.sync.aligned.m8n8.x4.trans.shared.b16 {%0,%1,%2,%3}, [%4];"
                 : "=r"(r[0]), "=r"(r[1]), "=r"(r[2]), "=r"(r[3]) : "r"(a));
}
__device__ __forceinline__ void mma_f16(float* c, const uint32_t* a, const uint32_t* b)
{
    asm volatile(
        "mma.sync.aligned.m16n8k16.row.col.f32.f16.f16.f32 "
        "{%0,%1,%2,%3}, {%4,%5,%6,%7}, {%8,%9}, {%0,%1,%2,%3};"
        : "+f"(c[0]), "+f"(c[1]), "+f"(c[2]), "+f"(c[3])
        : "r"(a[0]), "r"(a[1]), "r"(a[2]), "r"(a[3]), "r"(b[0]), "r"(b[1]));
}
__device__ __forceinline__ void cp16(uint32_t saddr, const void* g)
{
    asm volatile("cp.async.cg.shared.global [%0], [%1], 16;" :: "r"(saddr), "l"(g));
}
#define CP_COMMIT() asm volatile("cp.async.commit_group;")
#define CP_WAIT(n)  asm volatile("cp.async.wait_group %0;" :: "n"(n))
#define BARN(id, cnt) asm volatile("bar.sync %0, %1;" :: "r"(id), "r"(cnt) : "memory")

__device__ __forceinline__ float ex2(float x)
{
    float r;
    asm("ex2.approx.ftz.f32 %0, %1;" : "=f"(r) : "f"(x));
    return r;
}
__device__ __forceinline__ uint32_t ex2h2(uint32_t x)
{
    uint32_t r;
    asm("ex2.approx.f16x2 %0, %1;" : "=r"(r) : "r"(x));
    return r;
}
__device__ __forceinline__ uint32_t packh2(float lo, float hi)
{
    __half2 h = __floats2half2_rn(lo, hi);
    return *reinterpret_cast<uint32_t*>(&h);
}

// ---------------------------------------------------------------------------
// fp16 GEMM (FROZEN champion config): CTA 128x128, BK=64, 8 warps (4m x 2n),
// 3-stage cp.async pipeline, 2 CTAs/SM.
// mode 0: C fp32 (Wo)   mode 4: fused QKV
// ---------------------------------------------------------------------------
#define A_ST 72
#define B_ST 136
#define A_SZ (128 * A_ST)
#define B_SZ (64 * B_ST)
#define GSMEM (3 * (A_SZ + B_SZ) * 2)

__global__ __launch_bounds__(256, 2) void gemm_f16(
    const __half* __restrict__ A, const __half* __restrict__ B0,
    const __half* __restrict__ B1, const __half* __restrict__ B2,
    float* __restrict__ C, int K, int mode)
{
    extern __shared__ __half smem[];
    __half* As = smem;
    __half* Bs = smem + 3 * A_SZ;

    const int tid = threadIdx.x, lane = tid & 31, wid = tid >> 5;
    const int wm = wid & 3, wn = wid >> 2;
    const int g = lane >> 2, t = lane & 3;
    const int m0 = blockIdx.y * 128;
    int n0 = blockIdx.x * 128;
    const __half* Bm = B0;
    int Nb = DM;
    int vmode = mode;
    if (mode == 4) {
        if (blockIdx.x < 16) {
            vmode = 1;
        } else if (blockIdx.x < 20) {
            Bm = B1; Nb = 512; n0 = (blockIdx.x - 16) * 128; vmode = 2;
        } else {
            Bm = B2; Nb = 512; n0 = (blockIdx.x - 20) * 128; vmode = 3;
        }
    }

    const uint32_t sA = smem_u32(As), sB = smem_u32(Bs);
    const int niter = K >> 6;

    float acc[2][8][4];
#pragma unroll
    for (int mf = 0; mf < 2; mf++)
#pragma unroll
        for (int nt = 0; nt < 8; nt++)
#pragma unroll
            for (int r = 0; r < 4; r++) acc[mf][nt][r] = 0.f;

    auto issue = [&](int it) {
        if (it >= niter) return;
        int kt = it << 6;
        int st = it % 3;
#pragma unroll
        for (int u = 0; u < 4; u++) {
            int c = tid + 256 * u;
            int r = c >> 3, q = c & 7;
            cp16(sA + (st * A_SZ + r * A_ST + q * 8) * 2,
                 &A[(size_t)(m0 + r) * K + kt + q * 8]);
        }
#pragma unroll
        for (int u = 0; u < 4; u++) {
            int c = tid + 256 * u;
            int r = c >> 4, q = c & 15;
            cp16(sB + (st * B_SZ + r * B_ST + q * 8) * 2,
                 &Bm[(size_t)(kt + r) * Nb + n0 + q * 8]);
        }
    };

    issue(0); CP_COMMIT();
    issue(1); CP_COMMIT();

    for (int i = 0; i < niter; i++) {
        CP_WAIT(1);
        __syncthreads();
        const int st = i % 3;
        const uint32_t ab = sA + st * A_SZ * 2;
        const uint32_t bb = sB + st * B_SZ * 2;
        issue(i + 2);
        CP_COMMIT();
#pragma unroll
        for (int ks = 0; ks < 4; ks++) {
            const int kb = ks * 16;
            uint32_t af[2][4], bf[8][2];
#pragma unroll
            for (int mf = 0; mf < 2; mf++)
                ldmx4(af[mf], ab + ((wm * 32 + mf * 16 + (lane & 15)) * A_ST +
                                    kb + (lane >> 4) * 8) * 2);
#pragma unroll
            for (int p = 0; p < 4; p++) {
                uint32_t r[4];
                ldmx4t(r, bb + ((kb + (lane & 15)) * B_ST +
                                wn * 64 + p * 16 + (lane >> 4) * 8) * 2);
                bf[2 * p][0] = r[0]; bf[2 * p][1] = r[1];
                bf[2 * p + 1][0] = r[2]; bf[2 * p + 1][1] = r[3];
            }
#pragma unroll
            for (int mf = 0; mf < 2; mf++)
#pragma unroll
                for (int nt = 0; nt < 8; nt++)
                    mma_f16(acc[mf][nt], af[mf], bf[nt]);
        }
    }

    if (mode == 0) {
#pragma unroll
        for (int mf = 0; mf < 2; mf++) {
            int r = m0 + wm * 32 + mf * 16 + g;
#pragma unroll
            for (int nt = 0; nt < 8; nt++) {
                int col = n0 + wn * 64 + nt * 8 + t * 2;
                *(float2*)&C[(size_t)r * DM + col] =
                    make_float2(acc[mf][nt][0], acc[mf][nt][1]);
                *(float2*)&C[(size_t)(r + 8) * DM + col] =
                    make_float2(acc[mf][nt][2], acc[mf][nt][3]);
            }
        }
        return;
    }

#pragma unroll
    for (int mf = 0; mf < 2; mf++) {
#pragma unroll
        for (int hh = 0; hh < 2; hh++) {
            int row = m0 + wm * 32 + mf * 16 + g + hh * 8;
            int b = row >> 11;
            int s = row & (SEQ - 1);
#pragma unroll
            for (int nt = 0; nt < 8; nt++) {
                int col = n0 + wn * 64 + nt * 8 + t * 2;
                float v0 = acc[mf][nt][hh * 2 + 0];
                float v1 = acc[mf][nt][hh * 2 + 1];
                int d0 = col & 63;
                if (vmode != 3) {
                    int j0 = d0 & 31, j1 = (d0 + 1) & 31;
                    float2 cs0 = *(const float2*)&g_rope[((size_t)s * 32 + j0) * 2];
                    float2 cs1 = *(const float2*)&g_rope[((size_t)s * 32 + j1) * 2];
                    float o0 = v0 * cs0.x - v1 * cs0.y;
                    float o1 = v1 * cs1.x + v0 * cs1.y;
                    if (vmode == 1) { o0 *= QSCALE; o1 *= QSCALE; }
                    v0 = o0; v1 = o1;
                }
                int h = col >> 6;
                __half2 hv = __floats2half2_rn(v0, v1);
                if (vmode == 1)
                    *(__half2*)&g_q[(((size_t)b * NUM_HEADS + h) * SEQ + s) * HD + d0] = hv;
                else if (vmode == 2)
                    *(__half2*)&g_k[(((size_t)b * NUM_KV + h) * SEQ + s) * HD + d0] = hv;
                else
                    *(__half2*)&g_v[(((size_t)b * NUM_KV + h) * SEQ + s) * HD + d0] = hv;
            }
        }
    }
}

// ---------------------------------------------------------------------------
// fp16 mma flash attention v4: two-stream KV-split with 3-stage KV ring.
// Triple buffering makes the trailing per-tile barrier redundant (buffer
// (j+2)%3 was last read at iter j-1; the leading barrier of iter j proves all
// threads passed it), and lets issue_kv(j+2) move to the TOP of the loop so
// cp.async overlaps the whole compute phase. One bar.sync per tile per group.
// ---------------------------------------------------------------------------
#define FSTR 72
#define FA_Q_ELE (128 * FSTR)
#define FA_KV_ELE (64 * FSTR)
// Q + 2 groups x 3 stages x (K + V)
#define FA_SMEM ((FA_Q_ELE + 12 * FA_KV_ELE) * 2)

__global__ __launch_bounds__(512, 1) void fa_f16()
{
    extern __shared__ __half sm[];
    __half* q_s = sm;

    const int tid = threadIdx.x, lane = tid & 31, wid = tid >> 5;
    const int grp = wid >> 3;
    const int wg  = wid & 7;
    const int ltid = tid & 255;
    const int g = lane >> 2, t = lane & 3;
    const int qs = ((int)gridDim.x - 1 - (int)blockIdx.x) * 128;  // heavy first
    const int h = blockIdx.y, b = blockIdx.z;
    const int kvh = h >> 2;

    const __half* qg = &g_q[(((size_t)b * NUM_HEADS + h) * SEQ + qs) * HD];
    const __half* kg = &g_k[(((size_t)b * NUM_KV + kvh) * SEQ) * HD];
    const __half* vg = &g_v[(((size_t)b * NUM_KV + kvh) * SEQ) * HD];

    const uint32_t sq = smem_u32(q_s);
    const uint32_t sk0 = sq + FA_Q_ELE * 2;
    const uint32_t sv0 = sk0 + 6 * FA_KV_ELE * 2;

#pragma unroll
    for (int u = 0; u < 2; u++) {
        int c = tid + 512 * u;
        int r = c >> 3, q = c & 7;
        cp16(sq + (r * FSTR + q * 8) * 2, qg + (size_t)r * 64 + q * 8);
    }
    CP_COMMIT();
    CP_WAIT(0);
    __syncthreads();

    const int ntiles = qs / 64 + 2;
    const int nown = (ntiles - grp + 1) >> 1;

    auto issue_kv = [&](int j) {      // own tile j -> global tile grp+2j
        if (j >= nown) return;
        int koff = (grp + 2 * j) * 64;
        int st = j % 3;
        uint32_t kb = sk0 + (grp * 3 + st) * FA_KV_ELE * 2;
        uint32_t vb = sv0 + (grp * 3 + st) * FA_KV_ELE * 2;
#pragma unroll
        for (int u = 0; u < 2; u++) {
            int c = ltid + 256 * u;
            int r = c >> 3, q = c & 7;
            cp16(kb + (r * FSTR + q * 8) * 2, kg + (size_t)(koff + r) * 64 + q * 8);
            cp16(vb + (r * FSTR + q * 8) * 2, vg + (size_t)(koff + r) * 64 + q * 8);
        }
    };

    issue_kv(0); CP_COMMIT();
    issue_kv(1); CP_COMMIT();

    float o[8][4];
#pragma unroll
    for (int p = 0; p < 8; p++)
#pragma unroll
        for (int r = 0; r < 4; r++) o[p][r] = 0.f;
    float m0r = -1e30f, m1r = -1e30f, l0 = 0.f, l1 = 0.f;
    uint32_t qf[4][4];
#pragma unroll
    for (int kc = 0; kc < 4; kc++)
        ldmx4(qf[kc], sq + ((wg * 16 + (lane & 15)) * FSTR +
                            kc * 16 + (lane >> 4) * 8) * 2);

    const int barid = 1 + grp;

    for (int j = 0; j < nown; j++) {
        CP_WAIT(1);
        BARN(barid, 256);
        // buffer (j+2)%3 was last read at iter j-1; all 256 threads are past
        // that compute (leading barrier), so refill it NOW and overlap.
        issue_kv(j + 2);
        CP_COMMIT();

        const int st = j % 3;
        const uint32_t kb = sk0 + (grp * 3 + st) * FA_KV_ELE * 2;
        const uint32_t vb = sv0 + (grp * 3 + st) * FA_KV_ELE * 2;

        // S = Q @ K^T (scale pre-folded into Q)
        float s[8][4];
#pragma unroll
        for (int p = 0; p < 8; p++)
#pragma unroll
            for (int r = 0; r < 4; r++) s[p][r] = 0.f;
#pragma unroll
        for (int kc = 0; kc < 4; kc++) {
#pragma unroll
            for (int p = 0; p < 4; p++) {
                uint32_t r[4];
                ldmx4(r, kb + ((p * 16 + (lane & 7) + ((lane >> 4) & 1) * 8) * FSTR +
                               kc * 16 + ((lane >> 3) & 1) * 8) * 2);
                mma_f16(s[2 * p], qf[kc], r);
                mma_f16(s[2 * p + 1], qf[kc], r + 2);
            }
        }

        // causal mask on boundary tiles
        const int kt = (grp + 2 * j) * 64;
        const int rowg = qs + wg * 16 + g;
        if (kt + 63 > qs + wg * 16) {
#pragma unroll
            for (int p = 0; p < 8; p++) {
                int col = kt + p * 8 + 2 * t;
                if (col > rowg)     s[p][0] = -1e30f;
                if (col + 1 > rowg) s[p][1] = -1e30f;
                if (col > rowg + 8)     s[p][2] = -1e30f;
                if (col + 1 > rowg + 8) s[p][3] = -1e30f;
            }
        }

        // online softmax (rows g and g+8), quad reductions
        float mx0 = -1e30f, mx1 = -1e30f;
#pragma unroll
        for (int p = 0; p < 8; p++) {
            mx0 = fmaxf(mx0, fmaxf(s[p][0], s[p][1]));
            mx1 = fmaxf(mx1, fmaxf(s[p][2], s[p][3]));
        }
        mx0 = fmaxf(mx0, __shfl_xor_sync(0xffffffffu, mx0, 1));
        mx0 = fmaxf(mx0, __shfl_xor_sync(0xffffffffu, mx0, 2));
        mx1 = fmaxf(mx1, __shfl_xor_sync(0xffffffffu, mx1, 1));
        mx1 = fmaxf(mx1, __shfl_xor_sync(0xffffffffu, mx1, 2));
        float mn0 = fmaxf(m0r, mx0), mn1 = fmaxf(m1r, mx1);
        float a0 = ex2(m0r - mn0), a1 = ex2(m1r - mn1);
        m0r = mn0; m1r = mn1;

        __half2 acc0 = __floats2half2_rn(0.f, 0.f);
        __half2 acc1 = acc0;
        uint32_t pf[4][4];
#pragma unroll
        for (int p = 0; p < 8; p++) {
            uint32_t e0 = ex2h2(packh2(s[p][0] - mn0, s[p][1] - mn0));
            uint32_t e1 = ex2h2(packh2(s[p][2] - mn1, s[p][3] - mn1));
            acc0 = __hadd2(acc0, *reinterpret_cast<__half2*>(&e0));
            acc1 = __hadd2(acc1, *reinterpret_cast<__half2*>(&e1));
            int kc = p >> 1;
            if ((p & 1) == 0) { pf[kc][0] = e0; pf[kc][1] = e1; }
            else              { pf[kc][2] = e0; pf[kc][3] = e1; }
        }
        float ps0 = __low2float(acc0) + __high2float(acc0);
        float ps1 = __low2float(acc1) + __high2float(acc1);
        ps0 += __shfl_xor_sync(0xffffffffu, ps0, 1);
        ps0 += __shfl_xor_sync(0xffffffffu, ps0, 2);
        ps1 += __shfl_xor_sync(0xffffffffu, ps1, 1);
        ps1 += __shfl_xor_sync(0xffffffffu, ps1, 2);
        l0 = l0 * a0 + ps0;
        l1 = l1 * a1 + ps1;
#pragma unroll
        for (int p = 0; p < 8; p++) {
            o[p][0] *= a0; o[p][1] *= a0;
            o[p][2] *= a1; o[p][3] *= a1;
        }

        // O += P @ V
#pragma unroll
        for (int kc = 0; kc < 4; kc++) {
#pragma unroll
            for (int p = 0; p < 4; p++) {
                uint32_t r[4];
                ldmx4t(r, vb + ((kc * 16 + (lane & 15)) * FSTR +
                                p * 16 + ((lane >> 4) & 1) * 8) * 2);
                mma_f16(o[2 * p], pf[kc], r);
                mma_f16(o[2 * p + 1], pf[kc], r + 2);
            }
        }
        // no trailing barrier: 3-stage ring + leading barrier provide safety
    }

    // ---- merge the two streams ----
    __syncthreads();
    float* fb = (float*)(sm + FA_Q_ELE);
    const int midx = (wg * 32 + lane) * 36;
    if (grp == 1) {
#pragma unroll
        for (int p = 0; p < 8; p++) {
            fb[midx + p * 4 + 0] = o[p][0];
            fb[midx + p * 4 + 1] = o[p][1];
            fb[midx + p * 4 + 2] = o[p][2];
            fb[midx + p * 4 + 3] = o[p][3];
        }
        fb[midx + 32] = m0r;
        fb[midx + 33] = m1r;
        fb[midx + 34] = l0;
        fb[midx + 35] = l1;
    }
    __syncthreads();
    if (grp == 0) {
        float bm0 = fb[midx + 32], bm1 = fb[midx + 33];
        float bl0 = fb[midx + 34], bl1 = fb[midx + 35];
        float M0 = fmaxf(m0r, bm0), M1 = fmaxf(m1r, bm1);
        float a0 = ex2(m0r - M0), b0 = ex2(bm0 - M0);
        float a1 = ex2(m1r - M1), b1 = ex2(bm1 - M1);
        float inv0 = 1.f / (l0 * a0 + bl0 * b0);
        float inv1 = 1.f / (l1 * a1 + bl1 * b1);
        __half* og = &g_ao[((size_t)(b * SEQ + qs + wg * 16)) * DM + h * HD];
#pragma unroll
        for (int p = 0; p < 8; p++) {
            int col = p * 8 + 2 * t;
            float v0 = (o[p][0] * a0 + fb[midx + p * 4 + 0] * b0) * inv0;
            float v1 = (o[p][1] * a0 + fb[midx + p * 4 + 1] * b0) * inv0;
            float v2 = (o[p][2] * a1 + fb[midx + p * 4 + 2] * b1) * inv1;
            float v3 = (o[p][3] * a1 + fb[midx + p * 4 + 3] * b1) * inv1;
            *(__half2*)&og[(size_t)g * DM + col] = __floats2half2_rn(v0, v1);
            *(__half2*)&og[(size_t)(g + 8) * DM + col] = __floats2half2_rn(v2, v3);
        }
    }
}

// ---------------------------------------------------------------------------

extern "C" void kernel_launch(void* const* d_in, const int* in_sizes, int n_in,
                              void* d_out, int out_size)
{
    const float* x  = (const float*)d_in[0];
    const float* Wq = (const float*)d_in[2];
    const float* Wk = (const float*)d_in[3];
    const float* Wv = (const float*)d_in[4];
    const float* Wo = (const float*)d_in[5];
    float* out = (float*)d_out;

    void *xh, *wq, *wk, *wv, *wo, *ao;
    cudaGetSymbolAddress(&xh, g_xh);
    cudaGetSymbolAddress(&wq, g_wq);
    cudaGetSymbolAddress(&wk, g_wk);
    cudaGetSymbolAddress(&wv, g_wv);
    cudaGetSymbolAddress(&wo, g_wo);
    cudaGetSymbolAddress(&ao, g_ao);

    cudaFuncSetAttribute(gemm_f16, cudaFuncAttributeMaxDynamicSharedMemorySize, GSMEM);
    cudaFuncSetAttribute(fa_f16, cudaFuncAttributeMaxDynamicSharedMemorySize, FA_SMEM);

    // fused prologue: all conversions + rope table (one launch)
    prep<<<18688, 256>>>((const float4*)x, (const float4*)Wq, (const float4*)Wk,
                         (const float4*)Wv, (const float4*)Wo);

    // fused Q+K+V projections (RoPE on Q/K, scale folded into Q)
    gemm_f16<<<dim3(24, MTOT / 128), 256, GSMEM>>>(
        (const __half*)xh, (const __half*)wq, (const __half*)wk,
        (const __half*)wv, nullptr, DM, 4);

    // flash attention (two-stream KV-split, 3-stage ring, heavy-first)
    fa_f16<<<dim3(SEQ / 128, NUM_HEADS, B_DIM), 512, FA_SMEM>>>();

    // output projection
    gemm_f16<<<dim3(DM / 128, MTOT / 128), 256, GSMEM>>>(
        (const __half*)ao, (const __half*)wo, nullptr, nullptr, out, DM, 0);
}

// round 16
// speedup vs baseline: 1.0686x; 1.0686x over previous
#include <cuda_runtime.h>
#include <cuda_fp16.h>
#include <math.h>
#include <stdint.h>

#define B_DIM 2
#define NUM_HEADS 32
#define NUM_KV 8
#define SEQ 2048
#define DM 2048
#define HD 64
#define MTOT (B_DIM * SEQ)

// fp16 scratch (allocation-free device globals)
__device__ __half g_xh[(size_t)MTOT * DM];
__device__ __half g_wq[(size_t)DM * DM];
__device__ __half g_wk[(size_t)DM * 512];
__device__ __half g_wv[(size_t)DM * 512];
__device__ __half g_wo[(size_t)DM * DM];
__device__ __half g_q[(size_t)B_DIM * NUM_HEADS * SEQ * HD];
__device__ __half g_k[(size_t)B_DIM * NUM_KV * SEQ * HD];
__device__ __half g_v[(size_t)B_DIM * NUM_KV * SEQ * HD];
__device__ __half g_ao[(size_t)MTOT * DM];
__device__ float  g_rope[SEQ * 32 * 2];

// softmax scale folded into Q at projection time: 1/sqrt(64) * log2(e)
#define QSCALE 0.1803368801111204f

// ---------------------------------------------------------------------------
// Fused prologue: all fp32->fp16 conversions + RoPE table in ONE launch.
// 32B per thread (2x float4). Block ranges (in 512-float4 units):
//   x: 2,097,152 f4 -> 4096 blocks | Wq: 1,048,576 -> 2048 | Wk: 262,144 -> 512
//   Wv: 512 | Wo: 2048 | rope: 65,536 entries -> 256 blocks
// ---------------------------------------------------------------------------
__global__ void prep(const float4* __restrict__ x, const float4* __restrict__ wq,
                     const float4* __restrict__ wk, const float4* __restrict__ wv,
                     const float4* __restrict__ wo)
{
    const int b = blockIdx.x, tid = threadIdx.x;
    const float4* src;
    __half* dst;
    int base;
    if (b < 4096)      { src = x;  dst = g_xh; base = 0; }
    else if (b < 6144) { src = wq; dst = g_wq; base = 4096; }
    else if (b < 6656) { src = wk; dst = g_wk; base = 6144; }
    else if (b < 7168) { src = wv; dst = g_wv; base = 6656; }
    else if (b < 9216) { src = wo; dst = g_wo; base = 7168; }
    else {
        int i = (b - 9216) * 256 + tid;
        int s = i >> 5, j = i & 31;
        float inv = expf(-(float)j * 0.28782313662425572f);
        float sv, cv;
        sincosf((float)s * inv, &sv, &cv);
        g_rope[(size_t)i * 2 + 0] = cv;
        g_rope[(size_t)i * 2 + 1] = sv;
        return;
    }
    size_t i = ((size_t)(b - base) * 256 + tid) * 2;
#pragma unroll
    for (int u = 0; u < 2; u++) {
        float4 v = src[i + u];
        __half2* d = (__half2*)(dst + (i + u) * 4);
        d[0] = __floats2half2_rn(v.x, v.y);
        d[1] = __floats2half2_rn(v.z, v.w);
    }
}

// ---------------------------------------------------------------------------
// Helpers
// ---------------------------------------------------------------------------
__device__ __forceinline__ uint32_t smem_u32(const void* p)
{
    return (uint32_t)__cvta_generic_to_shared(p);
}
__device__ __forceinline__ void ldmx4(uint32_t* r, uint32_t a)
{
    asm volatile("ldmatrix.sync.aligned.m8n8.x4.shared.b16 {%0,%1,%2,%3}, [%4];"
                 : "=r"(r[0]), "=r"(r[1]), "=r"(r[2]), "=r"(r[3]) : "r"(a));
}
__device__ __forceinline__ void ldmx4t(uint32_t* r, uint32_t a)
{
    asm volatile("ldmatrix.sync.aligned.m8n8.x4.trans.shared.b16 {%0,%1,%2,%3}, [%4];"
                 : "=r"(r[0]), "=r"(r[1]), "=r"(r[2]), "=r"(r[3]) : "r"(a));
}
__device__ __forceinline__ void mma_f16(float* c, const uint32_t* a, const uint32_t* b)
{
    asm volatile(
        "mma.sync.aligned.m16n8k16.row.col.f32.f16.f16.f32 "
        "{%0,%1,%2,%3}, {%4,%5,%6,%7}, {%8,%9}, {%0,%1,%2,%3};"
        : "+f"(c[0]), "+f"(c[1]), "+f"(c[2]), "+f"(c[3])
        : "r"(a[0]), "r"(a[1]), "r"(a[2]), "r"(a[3]), "r"(b[0]), "r"(b[1]));
}
__device__ __forceinline__ void cp16(uint32_t saddr, const void* g)
{
    asm volatile("cp.async.cg.shared.global [%0], [%1], 16;" :: "r"(saddr), "l"(g));
}
#define CP_COMMIT() asm volatile("cp.async.commit_group;")
#define CP_WAIT(n)  asm volatile("cp.async.wait_group %0;" :: "n"(n))
#define BARN(id, cnt) asm volatile("bar.sync %0, %1;" :: "r"(id), "r"(cnt) : "memory")

__device__ __forceinline__ float ex2(float x)
{
    float r;
    asm("ex2.approx.ftz.f32 %0, %1;" : "=f"(r) : "f"(x));
    return r;
}
__device__ __forceinline__ uint32_t ex2h2(uint32_t x)
{
    uint32_t r;
    asm("ex2.approx.f16x2 %0, %1;" : "=r"(r) : "r"(x));
    return r;
}
__device__ __forceinline__ uint32_t packh2(float lo, float hi)
{
    __half2 h = __floats2half2_rn(lo, hi);
    return *reinterpret_cast<uint32_t*>(&h);
}

// ---------------------------------------------------------------------------
// fp16 GEMM (FROZEN R12 champion): CTA 128x128, BK=64, 8 warps (4m x 2n),
// 3-stage cp.async pipeline, 2 CTAs/SM, issue-at-bottom.
// mode 0: C fp32 (Wo)   mode 4: fused QKV
// ---------------------------------------------------------------------------
#define A_ST 72
#define B_ST 136
#define A_SZ (128 * A_ST)
#define B_SZ (64 * B_ST)
#define GSMEM (3 * (A_SZ + B_SZ) * 2)

__global__ __launch_bounds__(256, 2) void gemm_f16(
    const __half* __restrict__ A, const __half* __restrict__ B0,
    const __half* __restrict__ B1, const __half* __restrict__ B2,
    float* __restrict__ C, int K, int mode)
{
    extern __shared__ __half smem[];
    __half* As = smem;
    __half* Bs = smem + 3 * A_SZ;

    const int tid = threadIdx.x, lane = tid & 31, wid = tid >> 5;
    const int wm = wid & 3, wn = wid >> 2;
    const int g = lane >> 2, t = lane & 3;
    const int m0 = blockIdx.y * 128;
    int n0 = blockIdx.x * 128;
    const __half* Bm = B0;
    int Nb = DM;
    int vmode = mode;
    if (mode == 4) {
        if (blockIdx.x < 16) {
            vmode = 1;
        } else if (blockIdx.x < 20) {
            Bm = B1; Nb = 512; n0 = (blockIdx.x - 16) * 128; vmode = 2;
        } else {
            Bm = B2; Nb = 512; n0 = (blockIdx.x - 20) * 128; vmode = 3;
        }
    }

    const uint32_t sA = smem_u32(As), sB = smem_u32(Bs);
    const int niter = K >> 6;

    float acc[2][8][4];
#pragma unroll
    for (int mf = 0; mf < 2; mf++)
#pragma unroll
        for (int nt = 0; nt < 8; nt++)
#pragma unroll
            for (int r = 0; r < 4; r++) acc[mf][nt][r] = 0.f;

    auto issue = [&](int it) {
        if (it >= niter) return;
        int kt = it << 6;
        int st = it % 3;
#pragma unroll
        for (int u = 0; u < 4; u++) {
            int c = tid + 256 * u;
            int r = c >> 3, q = c & 7;
            cp16(sA + (st * A_SZ + r * A_ST + q * 8) * 2,
                 &A[(size_t)(m0 + r) * K + kt + q * 8]);
        }
#pragma unroll
        for (int u = 0; u < 4; u++) {
            int c = tid + 256 * u;
            int r = c >> 4, q = c & 15;
            cp16(sB + (st * B_SZ + r * B_ST + q * 8) * 2,
                 &Bm[(size_t)(kt + r) * Nb + n0 + q * 8]);
        }
    };

    issue(0); CP_COMMIT();
    issue(1); CP_COMMIT();

    for (int i = 0; i < niter; i++) {
        CP_WAIT(1);
        __syncthreads();
        const int st = i % 3;
        const uint32_t ab = sA + st * A_SZ * 2;
        const uint32_t bb = sB + st * B_SZ * 2;
#pragma unroll
        for (int ks = 0; ks < 4; ks++) {
            const int kb = ks * 16;
            uint32_t af[2][4], bf[8][2];
#pragma unroll
            for (int mf = 0; mf < 2; mf++)
                ldmx4(af[mf], ab + ((wm * 32 + mf * 16 + (lane & 15)) * A_ST +
                                    kb + (lane >> 4) * 8) * 2);
#pragma unroll
            for (int p = 0; p < 4; p++) {
                uint32_t r[4];
                ldmx4t(r, bb + ((kb + (lane & 15)) * B_ST +
                                wn * 64 + p * 16 + (lane >> 4) * 8) * 2);
                bf[2 * p][0] = r[0]; bf[2 * p][1] = r[1];
                bf[2 * p + 1][0] = r[2]; bf[2 * p + 1][1] = r[3];
            }
#pragma unroll
            for (int mf = 0; mf < 2; mf++)
#pragma unroll
                for (int nt = 0; nt < 8; nt++)
                    mma_f16(acc[mf][nt], af[mf], bf[nt]);
        }
        issue(i + 2);
        CP_COMMIT();
    }

    if (mode == 0) {
#pragma unroll
        for (int mf = 0; mf < 2; mf++) {
            int r = m0 + wm * 32 + mf * 16 + g;
#pragma unroll
            for (int nt = 0; nt < 8; nt++) {
                int col = n0 + wn * 64 + nt * 8 + t * 2;
                *(float2*)&C[(size_t)r * DM + col] =
                    make_float2(acc[mf][nt][0], acc[mf][nt][1]);
                *(float2*)&C[(size_t)(r + 8) * DM + col] =
                    make_float2(acc[mf][nt][2], acc[mf][nt][3]);
            }
        }
        return;
    }

#pragma unroll
    for (int mf = 0; mf < 2; mf++) {
#pragma unroll
        for (int hh = 0; hh < 2; hh++) {
            int row = m0 + wm * 32 + mf * 16 + g + hh * 8;
            int b = row >> 11;
            int s = row & (SEQ - 1);
#pragma unroll
            for (int nt = 0; nt < 8; nt++) {
                int col = n0 + wn * 64 + nt * 8 + t * 2;
                float v0 = acc[mf][nt][hh * 2 + 0];
                float v1 = acc[mf][nt][hh * 2 + 1];
                int d0 = col & 63;
                if (vmode != 3) {
                    int j0 = d0 & 31, j1 = (d0 + 1) & 31;
                    float2 cs0 = *(const float2*)&g_rope[((size_t)s * 32 + j0) * 2];
                    float2 cs1 = *(const float2*)&g_rope[((size_t)s * 32 + j1) * 2];
                    float o0 = v0 * cs0.x - v1 * cs0.y;
                    float o1 = v1 * cs1.x + v0 * cs1.y;
                    if (vmode == 1) { o0 *= QSCALE; o1 *= QSCALE; }
                    v0 = o0; v1 = o1;
                }
                int h = col >> 6;
                __half2 hv = __floats2half2_rn(v0, v1);
                if (vmode == 1)
                    *(__half2*)&g_q[(((size_t)b * NUM_HEADS + h) * SEQ + s) * HD + d0] = hv;
                else if (vmode == 2)
                    *(__half2*)&g_k[(((size_t)b * NUM_KV + h) * SEQ + s) * HD + d0] = hv;
                else
                    *(__half2*)&g_v[(((size_t)b * NUM_KV + h) * SEQ + s) * HD + d0] = hv;
            }
        }
    }
}

// ---------------------------------------------------------------------------
// fp16 mma flash attention (FROZEN R12 champion): two-stream KV-split.
// 512 threads = 2 warp-groups of 8 warps, each with own double-buffered K/V
// smem and named barrier; exact merge at the end.
// ---------------------------------------------------------------------------
#define FSTR 72
#define FA_Q_ELE (128 * FSTR)
#define FA_KV_ELE (64 * FSTR)
#define FA_SMEM ((FA_Q_ELE + 8 * FA_KV_ELE) * 2)

__global__ __launch_bounds__(512, 1) void fa_f16()
{
    extern __shared__ __half sm[];
    __half* q_s = sm;

    const int tid = threadIdx.x, lane = tid & 31, wid = tid >> 5;
    const int grp = wid >> 3;
    const int wg  = wid & 7;
    const int ltid = tid & 255;
    const int g = lane >> 2, t = lane & 3;
    const int qs = ((int)gridDim.x - 1 - (int)blockIdx.x) * 128;
    const int h = blockIdx.y, b = blockIdx.z;
    const int kvh = h >> 2;

    const __half* qg = &g_q[(((size_t)b * NUM_HEADS + h) * SEQ + qs) * HD];
    const __half* kg = &g_k[(((size_t)b * NUM_KV + kvh) * SEQ) * HD];
    const __half* vg = &g_v[(((size_t)b * NUM_KV + kvh) * SEQ) * HD];

    const uint32_t sq = smem_u32(q_s);
    const uint32_t sk0 = sq + FA_Q_ELE * 2;
    const uint32_t sv0 = sk0 + 4 * FA_KV_ELE * 2;

#pragma unroll
    for (int u = 0; u < 2; u++) {
        int c = tid + 512 * u;
        int r = c >> 3, q = c & 7;
        cp16(sq + (r * FSTR + q * 8) * 2, qg + (size_t)r * 64 + q * 8);
    }
    CP_COMMIT();
    CP_WAIT(0);
    __syncthreads();

    const int ntiles = qs / 64 + 2;
    const int nown = (ntiles - grp + 1) >> 1;

    auto issue_kv = [&](int j) {
        if (j >= nown) return;
        int koff = (grp + 2 * j) * 64;
        int st = j & 1;
        uint32_t kb = sk0 + (grp * 2 + st) * FA_KV_ELE * 2;
        uint32_t vb = sv0 + (grp * 2 + st) * FA_KV_ELE * 2;
#pragma unroll
        for (int u = 0; u < 2; u++) {
            int c = ltid + 256 * u;
            int r = c >> 3, q = c & 7;
            cp16(kb + (r * FSTR + q * 8) * 2, kg + (size_t)(koff + r) * 64 + q * 8);
            cp16(vb + (r * FSTR + q * 8) * 2, vg + (size_t)(koff + r) * 64 + q * 8);
        }
    };

    issue_kv(0); CP_COMMIT();
    issue_kv(1); CP_COMMIT();

    float o[8][4];
#pragma unroll
    for (int p = 0; p < 8; p++)
#pragma unroll
        for (int r = 0; r < 4; r++) o[p][r] = 0.f;
    float m0r = -1e30f, m1r = -1e30f, l0 = 0.f, l1 = 0.f;
    uint32_t qf[4][4];
#pragma unroll
    for (int kc = 0; kc < 4; kc++)
        ldmx4(qf[kc], sq + ((wg * 16 + (lane & 15)) * FSTR +
                            kc * 16 + (lane >> 4) * 8) * 2);

    const int barid = 1 + grp;

    for (int j = 0; j < nown; j++) {
        CP_WAIT(1);
        BARN(barid, 256);
        const int st = j & 1;
        const uint32_t kb = sk0 + (grp * 2 + st) * FA_KV_ELE * 2;
        const uint32_t vb = sv0 + (grp * 2 + st) * FA_KV_ELE * 2;

        float s[8][4];
#pragma unroll
        for (int p = 0; p < 8; p++)
#pragma unroll
            for (int r = 0; r < 4; r++) s[p][r] = 0.f;
#pragma unroll
        for (int kc = 0; kc < 4; kc++) {
#pragma unroll
            for (int p = 0; p < 4; p++) {
                uint32_t r[4];
                ldmx4(r, kb + ((p * 16 + (lane & 7) + ((lane >> 4) & 1) * 8) * FSTR +
                               kc * 16 + ((lane >> 3) & 1) * 8) * 2);
                mma_f16(s[2 * p], qf[kc], r);
                mma_f16(s[2 * p + 1], qf[kc], r + 2);
            }
        }

        const int kt = (grp + 2 * j) * 64;
        const int rowg = qs + wg * 16 + g;
        if (kt + 63 > qs + wg * 16) {
#pragma unroll
            for (int p = 0; p < 8; p++) {
                int col = kt + p * 8 + 2 * t;
                if (col > rowg)     s[p][0] = -1e30f;
                if (col + 1 > rowg) s[p][1] = -1e30f;
                if (col > rowg + 8)     s[p][2] = -1e30f;
                if (col + 1 > rowg + 8) s[p][3] = -1e30f;
            }
        }

        float mx0 = -1e30f, mx1 = -1e30f;
#pragma unroll
        for (int p = 0; p < 8; p++) {
            mx0 = fmaxf(mx0, fmaxf(s[p][0], s[p][1]));
            mx1 = fmaxf(mx1, fmaxf(s[p][2], s[p][3]));
        }
        mx0 = fmaxf(mx0, __shfl_xor_sync(0xffffffffu, mx0, 1));
        mx0 = fmaxf(mx0, __shfl_xor_sync(0xffffffffu, mx0, 2));
        mx1 = fmaxf(mx1, __shfl_xor_sync(0xffffffffu, mx1, 1));
        mx1 = fmaxf(mx1, __shfl_xor_sync(0xffffffffu, mx1, 2));
        float mn0 = fmaxf(m0r, mx0), mn1 = fmaxf(m1r, mx1);
        float a0 = ex2(m0r - mn0), a1 = ex2(m1r - mn1);
        m0r = mn0; m1r = mn1;

        __half2 acc0 = __floats2half2_rn(0.f, 0.f);
        __half2 acc1 = acc0;
        uint32_t pf[4][4];
#pragma unroll
        for (int p = 0; p < 8; p++) {
            uint32_t e0 = ex2h2(packh2(s[p][0] - mn0, s[p][1] - mn0));
            uint32_t e1 = ex2h2(packh2(s[p][2] - mn1, s[p][3] - mn1));
            acc0 = __hadd2(acc0, *reinterpret_cast<__half2*>(&e0));
            acc1 = __hadd2(acc1, *reinterpret_cast<__half2*>(&e1));
            int kc = p >> 1;
            if ((p & 1) == 0) { pf[kc][0] = e0; pf[kc][1] = e1; }
            else              { pf[kc][2] = e0; pf[kc][3] = e1; }
        }
        float ps0 = __low2float(acc0) + __high2float(acc0);
        float ps1 = __low2float(acc1) + __high2float(acc1);
        ps0 += __shfl_xor_sync(0xffffffffu, ps0, 1);
        ps0 += __shfl_xor_sync(0xffffffffu, ps0, 2);
        ps1 += __shfl_xor_sync(0xffffffffu, ps1, 1);
        ps1 += __shfl_xor_sync(0xffffffffu, ps1, 2);
        l0 = l0 * a0 + ps0;
        l1 = l1 * a1 + ps1;
#pragma unroll
        for (int p = 0; p < 8; p++) {
            o[p][0] *= a0; o[p][1] *= a0;
            o[p][2] *= a1; o[p][3] *= a1;
        }

#pragma unroll
        for (int kc = 0; kc < 4; kc++) {
#pragma unroll
            for (int p = 0; p < 4; p++) {
                uint32_t r[4];
                ldmx4t(r, vb + ((kc * 16 + (lane & 15)) * FSTR +
                                p * 16 + ((lane >> 4) & 1) * 8) * 2);
                mma_f16(o[2 * p], pf[kc], r);
                mma_f16(o[2 * p + 1], pf[kc], r + 2);
            }
        }

        BARN(barid, 256);
        issue_kv(j + 2);
        CP_COMMIT();
    }

    // merge the two streams
    __syncthreads();
    float* fb = (float*)(sm + FA_Q_ELE);
    const int midx = (wg * 32 + lane) * 36;
    if (grp == 1) {
#pragma unroll
        for (int p = 0; p < 8; p++) {
            fb[midx + p * 4 + 0] = o[p][0];
            fb[midx + p * 4 + 1] = o[p][1];
            fb[midx + p * 4 + 2] = o[p][2];
            fb[midx + p * 4 + 3] = o[p][3];
        }
        fb[midx + 32] = m0r;
        fb[midx + 33] = m1r;
        fb[midx + 34] = l0;
        fb[midx + 35] = l1;
    }
    __syncthreads();
    if (grp == 0) {
        float bm0 = fb[midx + 32], bm1 = fb[midx + 33];
        float bl0 = fb[midx + 34], bl1 = fb[midx + 35];
        float M0 = fmaxf(m0r, bm0), M1 = fmaxf(m1r, bm1);
        float a0 = ex2(m0r - M0), b0 = ex2(bm0 - M0);
        float a1 = ex2(m1r - M1), b1 = ex2(bm1 - M1);
        float inv0 = 1.f / (l0 * a0 + bl0 * b0);
        float inv1 = 1.f / (l1 * a1 + bl1 * b1);
        __half* og = &g_ao[((size_t)(b * SEQ + qs + wg * 16)) * DM + h * HD];
#pragma unroll
        for (int p = 0; p < 8; p++) {
            int col = p * 8 + 2 * t;
            float v0 = (o[p][0] * a0 + fb[midx + p * 4 + 0] * b0) * inv0;
            float v1 = (o[p][1] * a0 + fb[midx + p * 4 + 1] * b0) * inv0;
            float v2 = (o[p][2] * a1 + fb[midx + p * 4 + 2] * b1) * inv1;
            float v3 = (o[p][3] * a1 + fb[midx + p * 4 + 3] * b1) * inv1;
            *(__half2*)&og[(size_t)g * DM + col] = __floats2half2_rn(v0, v1);
            *(__half2*)&og[(size_t)(g + 8) * DM + col] = __floats2half2_rn(v2, v3);
        }
    }
}

// ---------------------------------------------------------------------------

extern "C" void kernel_launch(void* const* d_in, const int* in_sizes, int n_in,
                              void* d_out, int out_size)
{
    const float* x  = (const float*)d_in[0];
    const float* Wq = (const float*)d_in[2];
    const float* Wk = (const float*)d_in[3];
    const float* Wv = (const float*)d_in[4];
    const float* Wo = (const float*)d_in[5];
    float* out = (float*)d_out;

    void *xh, *wq, *wk, *wv, *wo, *ao;
    cudaGetSymbolAddress(&xh, g_xh);
    cudaGetSymbolAddress(&wq, g_wq);
    cudaGetSymbolAddress(&wk, g_wk);
    cudaGetSymbolAddress(&wv, g_wv);
    cudaGetSymbolAddress(&wo, g_wo);
    cudaGetSymbolAddress(&ao, g_ao);

    cudaFuncSetAttribute(gemm_f16, cudaFuncAttributeMaxDynamicSharedMemorySize, GSMEM);
    cudaFuncSetAttribute(fa_f16, cudaFuncAttributeMaxDynamicSharedMemorySize, FA_SMEM);

    // fused prologue: all conversions + rope table (one launch, 32B/thread)
    prep<<<9472, 256>>>((const float4*)x, (const float4*)Wq, (const float4*)Wk,
                        (const float4*)Wv, (const float4*)Wo);

    // fused Q+K+V projections (RoPE on Q/K, scale folded into Q)
    gemm_f16<<<dim3(24, MTOT / 128), 256, GSMEM>>>(
        (const __half*)xh, (const __half*)wq, (const __half*)wk,
        (const __half*)wv, nullptr, DM, 4);

    // flash attention (two-stream KV-split, heavy-first)
    fa_f16<<<dim3(SEQ / 128, NUM_HEADS, B_DIM), 512, FA_SMEM>>>();

    // output projection
    gemm_f16<<<dim3(DM / 128, MTOT / 128), 256, GSMEM>>>(
        (const __half*)ao, (const __half*)wo, nullptr, nullptr, out, DM, 0);
}